// round 13
// baseline (speedup 1.0000x reference)
#include <cuda_runtime.h>
#include <math.h>

#define NE   16
#define NU   8
#define NA   4
#define NSV  256
#define NPV  32
#define NFB  4
#define NDET 16
#define SVO  832   // 3*256 + 2*32

// per-walker shared context (floats)
#define OFF_SV    0        // 16*256 = 4096
#define OFF_PV    4096     // 256*32 = 8192   (s_in + detS alias here)
#define OFF_MU    12288    // 256             (logd/sign/env alias here at the end)
#define OFF_MD    12544    // 256
#define OFF_PU    12800    // 512
#define OFF_PD    13312    // 512
#define OFF_COM   13824    // 512             (r_s/a_s alias here early)
#define CTX       14336
#define SMEM_FLOATS (2*CTX)
#define SMEM_BYTES  (SMEM_FLOATS * 4)

__device__ __forceinline__ float tanh_fast(float x) {
    float e = __expf(2.0f * x);
    return 1.0f - __fdividef(2.0f, e + 1.0f);
}

__global__ void __launch_bounds__(512, 1) ansatz_kernel(
    const float* __restrict__ r,    const float* __restrict__ a,
    const float* __restrict__ sW0,  const float* __restrict__ sb0,
    const float* __restrict__ sW,   const float* __restrict__ sb,
    const float* __restrict__ pW0,  const float* __restrict__ pb0,
    const float* __restrict__ pW,   const float* __restrict__ pb,
    const float* __restrict__ vW,   const float* __restrict__ vb,
    const float* __restrict__ wuW,  const float* __restrict__ wub,
    const float* __restrict__ wdW,  const float* __restrict__ wdb,
    const float* __restrict__ wfW,  float* __restrict__ out)
{
    extern __shared__ float sm[];
    const int t  = threadIdx.x;
    const int w  = t >> 8;          // walker half (per-walker phases)
    const int tt = t & 255;
    const int bw = blockIdx.x * 2 + w;

    // per-walker context pointers (for the "halved" phases)
    float* ctx  = sm + w * CTX;
    float* s_v  = ctx + OFF_SV;
    float* p_v  = ctx + OFF_PV;
    float* mu   = ctx + OFF_MU;
    float* md   = ctx + OFF_MD;
    float* pu   = ctx + OFF_PU;
    float* pd   = ctx + OFF_PD;
    float* s_in = ctx + OFF_PV;          // alias (dead before p_v written)
    float* r_s  = ctx + OFF_COM;         // alias (dead before com written)
    float* a_s  = ctx + OFF_COM + 48;
    float* detS   = ctx + OFF_PV;        // alias (p_v dead by orbital phase)
    float* logd_s = ctx + OFF_MU;
    float* sign_s = ctx + OFF_MU + 32;
    float* env    = ctx + OFF_MU + 64;

    if (tt < 48)              r_s[tt]      = r[bw * 48 + tt];
    if (tt >= 64 && tt < 76)  a_s[tt - 64] = a[tt - 64];
    __syncthreads();

    // ---------------- embedding: s_in (per-walker) ----------------
    {
        int e = tt >> 4, f = tt & 15, atom = f >> 2, comp = f & 3;
        float dx = r_s[e*3+0] - a_s[atom*3+0];
        float dy = r_s[e*3+1] - a_s[atom*3+1];
        float dz = r_s[e*3+2] - a_s[atom*3+2];
        float v;
        if      (comp == 0) v = dx;
        else if (comp == 1) v = dy;
        else if (comp == 2) v = dz;
        else                v = sqrtf(dx*dx + dy*dy + dz*dz);
        s_in[tt] = v;
    }
    __syncthreads();

    // ---------------- stats for layer 0 (per-walker) ----------------
    if (tt < 16) {
        float s = 0.f;
        #pragma unroll
        for (int e = 0; e < NU; e++) s += s_in[e*16 + tt];
        mu[tt] = s * 0.125f;
    } else if (tt < 32) {
        int f = tt - 16; float s = 0.f;
        #pragma unroll
        for (int e = NU; e < NE; e++) s += s_in[e*16 + f];
        md[f] = s * 0.125f;
    } else if (tt < 160) {
        int idx = tt - 32;
        int half = idx >> 6;
        idx &= 63;
        int j = idx >> 2, c = idx & 3;
        int ib = half * 8;
        float rjx = r_s[j*3+0], rjy = r_s[j*3+1], rjz = r_s[j*3+2];
        float s = 0.f;
        #pragma unroll
        for (int ii = 0; ii < 8; ii++) {
            int i = ib + ii;
            float dx = rjx - r_s[i*3+0];
            float dy = rjy - r_s[i*3+1];
            float dz = rjz - r_s[i*3+2];
            float v;
            if      (c == 0) v = dx;
            else if (c == 1) v = dy;
            else if (c == 2) v = dz;
            else {
                float o = (i == j) ? 1.f : 0.f;
                float ex = dx + o, ey = dy + o, ez = dz + o;
                v = sqrtf(ex*ex + ey*ey + ez*ez);
            }
            s += v;
        }
        if (half == 0) pu[j*4 + c] = s * 0.125f;
        else           pd[j*4 + c] = s * 0.125f;
    }
    __syncthreads();

    // ---------------- layer 0, s-stream (per-walker; c = tt) ----------------
    float smu, smd;
    {
        const int c = tt;
        float common = sb0[c];
        #pragma unroll
        for (int k = 0; k < 16; k++)
            common += mu[k] * sW0[(16 + k)*NSV + c] + md[k] * sW0[(32 + k)*NSV + c];
        float acc[NE];
        #pragma unroll
        for (int e = 0; e < NE; e++) acc[e] = 0.f;
        #pragma unroll
        for (int k = 0; k < 16; k++) {
            float wv = sW0[k*NSV + c];
            #pragma unroll
            for (int e = 0; e < NE; e++) acc[e] += s_in[e*16 + k] * wv;
        }
        #pragma unroll
        for (int k = 0; k < 4; k++) {
            float wA = sW0[(48 + k)*NSV + c];
            float wB = sW0[(52 + k)*NSV + c];
            #pragma unroll
            for (int e = 0; e < NE; e++)
                acc[e] += pu[e*4 + k] * wA + pd[e*4 + k] * wB;
        }
        smu = 0.f; smd = 0.f;
        #pragma unroll
        for (int e = 0; e < NE; e++) {
            float v = tanh_fast(acc[e] + common);
            s_v[e*NSV + c] = v;
            if (e < NU) smu += v; else smd += v;
        }
    }
    __syncthreads();   // s_in reads done; p_v may be written

    // ---------------- layer 0, p-stream (per-walker) ----------------
    {
        const int c2 = tt & 31, wp = tt >> 5;
        float w0 = pW0[0*NPV + c2], w1 = pW0[1*NPV + c2];
        float w2 = pW0[2*NPV + c2], w3 = pW0[3*NPV + c2];
        const float pbias = pb0[c2];
        float puA = 0.f, puB = 0.f, pdA = 0.f, pdB = 0.f;
        for (int pr = wp; pr < 256; pr += 8) {
            int i = pr >> 4, j = pr & 15;
            float dx = r_s[j*3+0] - r_s[i*3+0];
            float dy = r_s[j*3+1] - r_s[i*3+1];
            float dz = r_s[j*3+2] - r_s[i*3+2];
            float o = (i == j) ? 1.f : 0.f;
            float ex = dx + o, ey = dy + o, ez = dz + o;
            float len = sqrtf(ex*ex + ey*ey + ez*ez);
            float v = tanh_fast(pbias + dx*w0 + dy*w1 + dz*w2 + len*w3);
            p_v[pr*NPV + c2] = v;
            bool jA = ((pr >> 3) & 1) == 0;
            if (i < NU) { if (jA) puA += v; else puB += v; }
            else        { if (jA) pdA += v; else pdB += v; }
        }
        pu[wp*NPV + c2]       = puA * 0.125f;
        pu[(wp+8)*NPV + c2]   = puB * 0.125f;
        pd[wp*NPV + c2]       = pdA * 0.125f;
        pd[(wp+8)*NPV + c2]   = pdB * 0.125f;
        mu[tt] = smu * 0.125f;
        md[tt] = smd * 0.125f;
    }
    __syncthreads();

    // ---------------- residual layers + final v layer ----------------
    // paired main-GEMM mapping: t -> (electron group of 4, column pair), both walkers
    const int eg    = t >> 7;          // 0..3, warp-uniform
    const int cp    = t & 127;
    const int cA    = cp * 2;
    const int ebase = eg * 4;
    // paired common mapping: t -> (block mu/md, k half, column pair)
    const int bh    = t >> 8;
    const int ckh   = t & 1;
    const int ccA   = ((t >> 1) & 127) * 2;

    float* sv0g = sm + OFF_SV;
    float* sv1g = sm + CTX + OFF_SV;

    for (int L = 0; L <= NFB; L++) {
        const bool isV = (L == NFB);
        const float* W    = isV ? vW : (sW + (size_t)L * SVO * NSV);
        const float* bias = isV ? vb : (sb + L * NSV);

        float puA = 0.f, puB = 0.f, pdA = 0.f, pdB = 0.f;
        if (!isV) {
            // p-stream residual layer (per-walker halves; lane-private cols, in-place)
            const int c2 = tt & 31, wp = tt >> 5;
            const float* PW = pW + L * NPV * NPV + c2;
            float pw[32];
            #pragma unroll
            for (int k = 0; k < 32; k++) pw[k] = PW[k*NPV];
            const float pbias = pb[L*NPV + c2];
            for (int pr = wp; pr < 256; pr += 8) {
                float pacc = pbias;
                #pragma unroll
                for (int k = 0; k < 32; k += 4) {
                    float4 v4 = *(const float4*)(p_v + pr*NPV + k);
                    pacc += v4.x*pw[k] + v4.y*pw[k+1] + v4.z*pw[k+2] + v4.w*pw[k+3];
                }
                float v = tanh_fast(pacc) + p_v[pr*NPV + c2];
                p_v[pr*NPV + c2] = v;
                bool jA = ((pr >> 3) & 1) == 0;
                if ((pr >> 4) < NU) { if (jA) puA += v; else puB += v; }
                else                { if (jA) pdA += v; else pdB += v; }
            }
        }

        // ---- paired common matvec: one weight stream, both walkers' stats ----
        {
            const float* Wblk = W + (size_t)(256 + bh*256 + ckh*128) * NSV + ccA;
            const float* st0  = sm +       (bh ? OFF_MD : OFF_MU) + ckh*128;
            const float* st1  = sm + CTX + (bh ? OFF_MD : OFF_MU) + ckh*128;
            float a0 = 0.f, b0 = 0.f, a1 = 0.f, b1 = 0.f;
            for (int k = 0; k < 128; k += 4) {
                float2 q0 = *(const float2*)(Wblk + (k+0)*NSV);
                float2 q1 = *(const float2*)(Wblk + (k+1)*NSV);
                float2 q2 = *(const float2*)(Wblk + (k+2)*NSV);
                float2 q3 = *(const float2*)(Wblk + (k+3)*NSV);
                float4 m0 = *(const float4*)(st0 + k);
                float4 m1 = *(const float4*)(st1 + k);
                a0 += m0.x*q0.x + m0.y*q1.x + m0.z*q2.x + m0.w*q3.x;
                b0 += m0.x*q0.y + m0.y*q1.y + m0.z*q2.y + m0.w*q3.y;
                a1 += m1.x*q0.x + m1.y*q1.x + m1.z*q2.x + m1.w*q3.x;
                b1 += m1.x*q0.y + m1.y*q1.y + m1.z*q2.y + m1.w*q3.y;
            }
            a0 += __shfl_xor_sync(0xffffffffu, a0, 1);
            b0 += __shfl_xor_sync(0xffffffffu, b0, 1);
            a1 += __shfl_xor_sync(0xffffffffu, a1, 1);
            b1 += __shfl_xor_sync(0xffffffffu, b1, 1);
            float bx = 0.f, by = 0.f;
            if (bh == 0) { float2 b2 = *(const float2*)(bias + ccA); bx = b2.x; by = b2.y; }
            if (ckh == 0) {
                float2 cv; cv.x = a0 + bx; cv.y = b0 + by;
                *(float2*)(sm + OFF_COM + bh*256 + ccA) = cv;
            } else {
                float2 cv; cv.x = a1 + bx; cv.y = b1 + by;
                *(float2*)(sm + CTX + OFF_COM + bh*256 + ccA) = cv;
            }
        }

        // ---- paired main GEMM: 4 electrons x 2 cols x 2 walkers ----
        float a00[4], a01[4], a10[4], a11[4];   // a{walker}{col}[e]
        #pragma unroll
        for (int e = 0; e < 4; e++) { a00[e]=0.f; a01[e]=0.f; a10[e]=0.f; a11[e]=0.f; }
        {
            const float* Wc  = W + cA;
            const float* sv0 = sv0g + ebase*NSV;
            const float* sv1 = sv1g + ebase*NSV;
            for (int k = 0; k < 256; k += 4) {
                float2 w0 = *(const float2*)(Wc + (k+0)*NSV);
                float2 w1 = *(const float2*)(Wc + (k+1)*NSV);
                float2 w2 = *(const float2*)(Wc + (k+2)*NSV);
                float2 w3 = *(const float2*)(Wc + (k+3)*NSV);
                #pragma unroll
                for (int e = 0; e < 4; e++) {
                    float4 s0 = *(const float4*)(sv0 + e*NSV + k);
                    a00[e] += s0.x*w0.x + s0.y*w1.x + s0.z*w2.x + s0.w*w3.x;
                    a01[e] += s0.x*w0.y + s0.y*w1.y + s0.z*w2.y + s0.w*w3.y;
                    float4 s1 = *(const float4*)(sv1 + e*NSV + k);
                    a10[e] += s1.x*w0.x + s1.y*w1.x + s1.z*w2.x + s1.w*w3.x;
                    a11[e] += s1.x*w0.y + s1.y*w1.y + s1.z*w2.y + s1.w*w3.y;
                }
            }
        }
        // ---- paired pu block ----
        {
            const float* Wp  = W + (size_t)768*NSV + cA;
            const float* pv0 = sm +       OFF_PU + ebase*NPV;
            const float* pv1 = sm + CTX + OFF_PU + ebase*NPV;
            for (int k = 0; k < 32; k += 4) {
                float2 w0 = *(const float2*)(Wp + (k+0)*NSV);
                float2 w1 = *(const float2*)(Wp + (k+1)*NSV);
                float2 w2 = *(const float2*)(Wp + (k+2)*NSV);
                float2 w3 = *(const float2*)(Wp + (k+3)*NSV);
                #pragma unroll
                for (int e = 0; e < 4; e++) {
                    float4 s0 = *(const float4*)(pv0 + e*NPV + k);
                    a00[e] += s0.x*w0.x + s0.y*w1.x + s0.z*w2.x + s0.w*w3.x;
                    a01[e] += s0.x*w0.y + s0.y*w1.y + s0.z*w2.y + s0.w*w3.y;
                    float4 s1 = *(const float4*)(pv1 + e*NPV + k);
                    a10[e] += s1.x*w0.x + s1.y*w1.x + s1.z*w2.x + s1.w*w3.x;
                    a11[e] += s1.x*w0.y + s1.y*w1.y + s1.z*w2.y + s1.w*w3.y;
                }
            }
        }
        // ---- paired pd block ----
        {
            const float* Wp  = W + (size_t)800*NSV + cA;
            const float* pv0 = sm +       OFF_PD + ebase*NPV;
            const float* pv1 = sm + CTX + OFF_PD + ebase*NPV;
            for (int k = 0; k < 32; k += 4) {
                float2 w0 = *(const float2*)(Wp + (k+0)*NSV);
                float2 w1 = *(const float2*)(Wp + (k+1)*NSV);
                float2 w2 = *(const float2*)(Wp + (k+2)*NSV);
                float2 w3 = *(const float2*)(Wp + (k+3)*NSV);
                #pragma unroll
                for (int e = 0; e < 4; e++) {
                    float4 s0 = *(const float4*)(pv0 + e*NPV + k);
                    a00[e] += s0.x*w0.x + s0.y*w1.x + s0.z*w2.x + s0.w*w3.x;
                    a01[e] += s0.x*w0.y + s0.y*w1.y + s0.z*w2.y + s0.w*w3.y;
                    float4 s1 = *(const float4*)(pv1 + e*NPV + k);
                    a10[e] += s1.x*w0.x + s1.y*w1.x + s1.z*w2.x + s1.w*w3.x;
                    a11[e] += s1.x*w0.y + s1.y*w1.y + s1.z*w2.y + s1.w*w3.y;
                }
            }
        }

        __syncthreads();   // all reads + com writes complete

        // ---- writeback: both walkers, 4 electrons x 2 cols each ----
        {
            float2 c0m = *(const float2*)(sm + OFF_COM + cA);
            float2 c0d = *(const float2*)(sm + OFF_COM + 256 + cA);
            float2 c1m = *(const float2*)(sm + CTX + OFF_COM + cA);
            float2 c1d = *(const float2*)(sm + CTX + OFF_COM + 256 + cA);
            const float cm0x = c0m.x + c0d.x, cm0y = c0m.y + c0d.y;
            const float cm1x = c1m.x + c1d.x, cm1y = c1m.y + c1d.y;
            if (!isV) {
                #pragma unroll
                for (int e = 0; e < 4; e++) {
                    float* d0 = sv0g + (ebase+e)*NSV + cA;
                    float2 o0 = *(const float2*)d0;
                    float2 n0;
                    n0.x = tanh_fast(a00[e] + cm0x) + o0.x;
                    n0.y = tanh_fast(a01[e] + cm0y) + o0.y;
                    *(float2*)d0 = n0;
                    float* d1 = sv1g + (ebase+e)*NSV + cA;
                    float2 o1 = *(const float2*)d1;
                    float2 n1;
                    n1.x = tanh_fast(a10[e] + cm1x) + o1.x;
                    n1.y = tanh_fast(a11[e] + cm1y) + o1.y;
                    *(float2*)d1 = n1;
                }
                // deferred pu/pd stores (per-walker partials from p-stream)
                const int c2 = tt & 31, wp = tt >> 5;
                pu[wp*NPV + c2]     = puA * 0.125f;
                pu[(wp+8)*NPV + c2] = puB * 0.125f;
                pd[wp*NPV + c2]     = pdA * 0.125f;
                pd[(wp+8)*NPV + c2] = pdB * 0.125f;
            } else {
                #pragma unroll
                for (int e = 0; e < 4; e++) {
                    float2 n0;
                    n0.x = tanh_fast(a00[e] + cm0x);
                    n0.y = tanh_fast(a01[e] + cm0y);
                    *(float2*)(sv0g + (ebase+e)*NSV + cA) = n0;
                    float2 n1;
                    n1.x = tanh_fast(a10[e] + cm1x);
                    n1.y = tanh_fast(a11[e] + cm1y);
                    *(float2*)(sv1g + (ebase+e)*NSV + cA) = n1;
                }
                if (tt < 16) {   // env recompute (mu region dead after v-layer common)
                    const float* rg = r + bw*48 + tt*3;
                    float ex = rg[0], ey = rg[1], ez = rg[2];
                    float s = 0.f;
                    #pragma unroll
                    for (int atom = 0; atom < NA; atom++) {
                        float dx = ex - a[atom*3+0];
                        float dy = ey - a[atom*3+1];
                        float dz = ez - a[atom*3+2];
                        s += __expf(-sqrtf(dx*dx + dy*dy + dz*dz));
                    }
                    env[tt] = s;
                }
            }
        }
        __syncthreads();

        if (!isV) {
            // ---- mu/md stats (per-walker; col = tt) ----
            const int c = tt;
            float su = 0.f, sd2 = 0.f;
            #pragma unroll
            for (int e = 0; e < NU; e++)  su  += s_v[e*NSV + c];
            #pragma unroll
            for (int e = NU; e < NE; e++) sd2 += s_v[e*NSV + c];
            mu[c] = su * 0.125f;
            md[c] = sd2 * 0.125f;
            __syncthreads();
        }
    }
    // p_v dead; detS aliases its storage.

    // ---------------- orbitals: paired (spin, egroup, col) x 2 walkers ----------------
    {
        const int ocol = t & 127;
        const int oeg  = (t >> 7) & 1;
        const int osp  = t >> 8;
        const float* W    = osp ? wdW : wuW;
        const float* bias = osp ? wdb : wub;
        const int eb2 = osp * 8 + oeg * 4;

        float o0[4], o1[4];
        #pragma unroll
        for (int ii = 0; ii < 4; ii++) { o0[ii] = 0.f; o1[ii] = 0.f; }
        const float* Wc2 = W + ocol;
        const float* sv0 = sv0g + eb2*NSV;
        const float* sv1 = sv1g + eb2*NSV;
        for (int k = 0; k < 256; k += 4) {
            float w0 = Wc2[(k+0)*128];
            float w1 = Wc2[(k+1)*128];
            float w2 = Wc2[(k+2)*128];
            float w3 = Wc2[(k+3)*128];
            #pragma unroll
            for (int ii = 0; ii < 4; ii++) {
                float4 s0 = *(const float4*)(sv0 + ii*NSV + k);
                o0[ii] += s0.x*w0 + s0.y*w1 + s0.z*w2 + s0.w*w3;
                float4 s1 = *(const float4*)(sv1 + ii*NSV + k);
                o1[ii] += s1.x*w0 + s1.y*w1 + s1.z*w2 + s1.w*w3;
            }
        }
        const int d = ocol & 15, j = ocol >> 4;
        const int detIdx = osp * NDET + d;
        const float bs = bias[ocol];
        float* det0 = sm +       OFF_PV;
        float* det1 = sm + CTX + OFF_PV;
        const float* env0 = sm +       OFF_MU + 64;
        const float* env1 = sm + CTX + OFF_MU + 64;
        #pragma unroll
        for (int ii = 0; ii < 4; ii++) {
            const int row = oeg*4 + ii;
            det0[detIdx*65 + row*8 + j] = (o0[ii] + bs) * env0[osp*8 + row];
            det1[detIdx*65 + row*8 + j] = (o1[ii] + bs) * env1[osp*8 + row];
        }
    }
    __syncthreads();

    // ---------------- slogdet: 64 independent 8x8 LU ----------------
    if (t < 64) {
        const int wI = t >> 5;
        float* base = sm + wI*CTX;
        float* M = base + OFF_PV + (t & 31) * 65;
        float sg = 1.f, ld = 0.f;
        for (int k = 0; k < 8; k++) {
            int p = k; float best = fabsf(M[k*8 + k]);
            for (int rr2 = k + 1; rr2 < 8; rr2++) {
                float v = fabsf(M[rr2*8 + k]);
                if (v > best) { best = v; p = rr2; }
            }
            if (p != k) {
                for (int cc = 0; cc < 8; cc++) {
                    float tmp = M[k*8 + cc]; M[k*8 + cc] = M[p*8 + cc]; M[p*8 + cc] = tmp;
                }
                sg = -sg;
            }
            float piv = M[k*8 + k];
            if (piv < 0.f) sg = -sg;
            ld += logf(fabsf(piv));
            float inv = 1.f / piv;
            for (int rr2 = k + 1; rr2 < 8; rr2++) {
                float f = M[rr2*8 + k] * inv;
                for (int cc = k + 1; cc < 8; cc++) M[rr2*8 + cc] -= f * M[k*8 + cc];
            }
        }
        base[OFF_MU + (t & 31)]      = ld;   // logd_s
        base[OFF_MU + 32 + (t & 31)] = sg;   // sign_s
    }
    __syncthreads();

    // ---------------- combine (one thread per walker) ----------------
    if (tt == 0) {
        float lds[NDET], sgs[NDET], m = -1e30f;
        #pragma unroll
        for (int d = 0; d < NDET; d++) {
            lds[d] = logd_s[d] + logd_s[NDET + d];
            sgs[d] = sign_s[d] * sign_s[NDET + d];
            if (lds[d] > m) m = lds[d];
        }
        float sum = 0.f;
        #pragma unroll
        for (int d = 0; d < NDET; d++)
            sum += sgs[d] * expf(lds[d] - m) * wfW[d];
        out[bw] = logf(fabsf(sum)) + m;
    }
}

extern "C" void kernel_launch(void* const* d_in, const int* in_sizes, int n_in,
                              void* d_out, int out_size)
{
    const float* r   = (const float*)d_in[0];
    const float* a   = (const float*)d_in[1];
    const float* sW0 = (const float*)d_in[2];
    const float* sb0 = (const float*)d_in[3];
    const float* sW  = (const float*)d_in[4];
    const float* sb  = (const float*)d_in[5];
    const float* pW0 = (const float*)d_in[6];
    const float* pb0 = (const float*)d_in[7];
    const float* pW  = (const float*)d_in[8];
    const float* pb  = (const float*)d_in[9];
    const float* vW  = (const float*)d_in[10];
    const float* vb  = (const float*)d_in[11];
    const float* wuW = (const float*)d_in[12];
    const float* wub = (const float*)d_in[13];
    const float* wdW = (const float*)d_in[14];
    const float* wdb = (const float*)d_in[15];
    const float* wfW = (const float*)d_in[16];
    float* out = (float*)d_out;

    const int B = in_sizes[0] / (NE * 3);

    cudaFuncSetAttribute(ansatz_kernel,
                         cudaFuncAttributeMaxDynamicSharedMemorySize, SMEM_BYTES);
    ansatz_kernel<<<B / 2, 512, SMEM_BYTES>>>(r, a, sW0, sb0, sW, sb, pW0, pb0,
                                              pW, pb, vW, vb, wuW, wub, wdW, wdb,
                                              wfW, out);
}

// round 14
// speedup vs baseline: 1.2412x; 1.2412x over previous
#include <cuda_runtime.h>
#include <math.h>

#define NE   16
#define NU   8
#define NA   4
#define NSV  256
#define NPV  32
#define NFB  4
#define NDET 16
#define SVO  832   // 3*256 + 2*32

// shared layout (floats) — 18432 floats = 73728 B -> 3 CTAs/SM
#define OFF_SV    0        // 16*256 = 4096
#define OFF_PV    4096     // 256*32 = 8192   (s_in + detS alias here)
#define OFF_MU    12288    // 256             (logd/sign/env alias here at the end)
#define OFF_MD    12544    // 256
#define OFF_PU    12800    // 512
#define OFF_PD    13312    // 512
#define OFF_COM   13824    // 512             (r_s/a_s alias here early)
#define OFF_SCR   14336    // 4096 float partial-reduction scratch
#define SMEM_FLOATS 18432
#define SMEM_BYTES  (SMEM_FLOATS * 4)

__device__ __forceinline__ float tanh_fast(float x) {
    float e = __expf(2.0f * x);
    return 1.0f - __fdividef(2.0f, e + 1.0f);
}

__global__ void __launch_bounds__(256, 3) ansatz_kernel(
    const float* __restrict__ r,    const float* __restrict__ a,
    const float* __restrict__ sW0,  const float* __restrict__ sb0,
    const float* __restrict__ sW,   const float* __restrict__ sb,
    const float* __restrict__ pW0,  const float* __restrict__ pb0,
    const float* __restrict__ pW,   const float* __restrict__ pb,
    const float* __restrict__ vW,   const float* __restrict__ vb,
    const float* __restrict__ wuW,  const float* __restrict__ wub,
    const float* __restrict__ wdW,  const float* __restrict__ wdb,
    const float* __restrict__ wfW,  float* __restrict__ out)
{
    extern __shared__ float sm[];
    float* s_v  = sm + OFF_SV;
    float* p_v  = sm + OFF_PV;
    float* mu   = sm + OFF_MU;
    float* md   = sm + OFF_MD;
    float* pu   = sm + OFF_PU;
    float* pd   = sm + OFF_PD;
    float* com  = sm + OFF_COM;
    float* scr  = sm + OFF_SCR;

    float* s_in = sm + OFF_PV;          // alias, dead before p_v written
    float* r_s  = sm + OFF_COM;         // alias, dead before com written
    float* a_s  = sm + OFF_COM + 48;
    float* detS   = sm + OFF_PV;        // alias, p_v dead by orbital phase
    float* logd_s = sm + OFF_MU;
    float* sign_s = sm + OFF_MU + 32;
    float* env    = sm + OFF_MU + 64;

    const int t = threadIdx.x;
    const int b = blockIdx.x;

    if (t < 48)              r_s[t]      = r[b * 48 + t];
    if (t >= 64 && t < 76)   a_s[t - 64] = a[t - 64];
    __syncthreads();

    // ---------------- embedding: s_in ----------------
    {
        int e = t >> 4, f = t & 15, atom = f >> 2, comp = f & 3;
        float dx = r_s[e*3+0] - a_s[atom*3+0];
        float dy = r_s[e*3+1] - a_s[atom*3+1];
        float dz = r_s[e*3+2] - a_s[atom*3+2];
        float v;
        if      (comp == 0) v = dx;
        else if (comp == 1) v = dy;
        else if (comp == 2) v = dz;
        else                v = sqrtf(dx*dx + dy*dy + dz*dz);
        s_in[t] = v;
    }
    __syncthreads();

    // ---------------- stats for layer 0 ----------------
    if (t < 16) {
        float s = 0.f;
        #pragma unroll
        for (int e = 0; e < NU; e++) s += s_in[e*16 + t];
        mu[t] = s * 0.125f;
    } else if (t < 32) {
        int f = t - 16; float s = 0.f;
        #pragma unroll
        for (int e = NU; e < NE; e++) s += s_in[e*16 + f];
        md[f] = s * 0.125f;
    } else if (t < 160) {
        int idx = t - 32;
        int half = idx >> 6;
        idx &= 63;
        int j = idx >> 2, c = idx & 3;
        int ib = half * 8;
        float rjx = r_s[j*3+0], rjy = r_s[j*3+1], rjz = r_s[j*3+2];
        float s = 0.f;
        #pragma unroll
        for (int ii = 0; ii < 8; ii++) {
            int i = ib + ii;
            float dx = rjx - r_s[i*3+0];
            float dy = rjy - r_s[i*3+1];
            float dz = rjz - r_s[i*3+2];
            float v;
            if      (c == 0) v = dx;
            else if (c == 1) v = dy;
            else if (c == 2) v = dz;
            else {
                float o = (i == j) ? 1.f : 0.f;
                float ex = dx + o, ey = dy + o, ez = dz + o;
                v = sqrtf(ex*ex + ey*ey + ez*ez);
            }
            s += v;
        }
        if (half == 0) pu[j*4 + c] = s * 0.125f;
        else           pd[j*4 + c] = s * 0.125f;
    }
    __syncthreads();

    // ---------------- layer 0, s-stream ----------------
    float smu, smd;
    {
        const int c = t;
        float common = sb0[c];
        #pragma unroll
        for (int k = 0; k < 16; k++)
            common += mu[k] * sW0[(16 + k)*NSV + c] + md[k] * sW0[(32 + k)*NSV + c];
        float acc[NE];
        #pragma unroll
        for (int e = 0; e < NE; e++) acc[e] = 0.f;
        #pragma unroll
        for (int k = 0; k < 16; k++) {
            float wv = sW0[k*NSV + c];
            #pragma unroll
            for (int e = 0; e < NE; e++) acc[e] += s_in[e*16 + k] * wv;
        }
        #pragma unroll
        for (int k = 0; k < 4; k++) {
            float wA = sW0[(48 + k)*NSV + c];
            float wB = sW0[(52 + k)*NSV + c];
            #pragma unroll
            for (int e = 0; e < NE; e++)
                acc[e] += pu[e*4 + k] * wA + pd[e*4 + k] * wB;
        }
        smu = 0.f; smd = 0.f;
        #pragma unroll
        for (int e = 0; e < NE; e++) {
            float v = tanh_fast(acc[e] + common);
            s_v[e*NSV + c] = v;
            if (e < NU) smu += v; else smd += v;
        }
    }
    __syncthreads();   // s_in reads done; p_v may be written

    // ---------------- layer 0, p-stream ----------------
    {
        const int c2 = t & 31, wp = t >> 5;
        float w0 = pW0[0*NPV + c2], w1 = pW0[1*NPV + c2];
        float w2 = pW0[2*NPV + c2], w3 = pW0[3*NPV + c2];
        const float pbias = pb0[c2];
        float puA = 0.f, puB = 0.f, pdA = 0.f, pdB = 0.f;
        for (int pr = wp; pr < 256; pr += 8) {
            int i = pr >> 4, j = pr & 15;
            float dx = r_s[j*3+0] - r_s[i*3+0];
            float dy = r_s[j*3+1] - r_s[i*3+1];
            float dz = r_s[j*3+2] - r_s[i*3+2];
            float o = (i == j) ? 1.f : 0.f;
            float ex = dx + o, ey = dy + o, ez = dz + o;
            float len = sqrtf(ex*ex + ey*ey + ez*ez);
            float v = tanh_fast(pbias + dx*w0 + dy*w1 + dz*w2 + len*w3);
            p_v[pr*NPV + c2] = v;
            bool jA = ((pr >> 3) & 1) == 0;
            if (i < NU) { if (jA) puA += v; else puB += v; }
            else        { if (jA) pdA += v; else pdB += v; }
        }
        pu[wp*NPV + c2]       = puA * 0.125f;
        pu[(wp+8)*NPV + c2]   = puB * 0.125f;
        pd[wp*NPV + c2]       = pdA * 0.125f;
        pd[(wp+8)*NPV + c2]   = pdB * 0.125f;
        mu[t] = smu * 0.125f;
        md[t] = smd * 0.125f;
    }
    __syncthreads();

    // ---------------- residual layers + final v layer ----------------
    // main GEMM mapping (all warp-uniform selectors):
    const int eh    = t >> 7;          // electron half
    const int kh    = (t >> 6) & 1;    // k half (partner warp = t ^ 64)
    const int cg    = (t >> 5) & 1;    // column group of 128
    const int lane  = t & 31;
    const int cA    = cg*128 + lane*4; // 4 adjacent cols
    const int ebase = eh * 8;
    const int kbase = kh * 128;
    const int pid   = eh*64 + cg*32 + lane;   // 0..127 (kh excluded)
    // common-matvec mapping (same as R6)
    const int bh    = t >> 7;
    const int ckh   = t & 1;
    const int ccA   = ((t >> 1) & 63) * 4;

    for (int L = 0; L <= NFB; L++) {
        const bool isV = (L == NFB);
        const float* W    = isV ? vW : (sW + (size_t)L * SVO * NSV);
        const float* bias = isV ? vb : (sb + L * NSV);

        float puA = 0.f, puB = 0.f, pdA = 0.f, pdB = 0.f;
        if (!isV) {
            // p-stream residual layer (lane-private columns, in-place)
            const int c2 = t & 31, wp = t >> 5;
            const float* PW = pW + L * NPV * NPV + c2;
            float pw[32];
            #pragma unroll
            for (int k = 0; k < 32; k++) pw[k] = PW[k*NPV];
            const float pbias = pb[L*NPV + c2];
            for (int pr = wp; pr < 256; pr += 8) {
                float pacc = pbias;
                #pragma unroll
                for (int k = 0; k < 32; k += 4) {
                    float4 v4 = *(const float4*)(p_v + pr*NPV + k);
                    pacc += v4.x*pw[k] + v4.y*pw[k+1] + v4.z*pw[k+2] + v4.w*pw[k+3];
                }
                float v = tanh_fast(pacc) + p_v[pr*NPV + c2];
                p_v[pr*NPV + c2] = v;
                bool jA = ((pr >> 3) & 1) == 0;
                if ((pr >> 4) < NU) { if (jA) puA += v; else puB += v; }
                else                { if (jA) pdA += v; else pdB += v; }
            }
        }

        // ---- common matvec (R6 scheme): (bh block) x (lane k half), 4 cols ----
        {
            const float* statv = (bh ? md : mu) + ckh * 128;
            const float* Wblk  = W + (size_t)(256 + bh*256 + ckh*128) * NSV + ccA;
            float c4x = 0.f, c4y = 0.f, c4z = 0.f, c4w = 0.f;
            for (int k = 0; k < 128; k += 4) {
                float4 m4 = *(const float4*)(statv + k);
                float4 w0 = *(const float4*)(Wblk + (k+0)*NSV);
                float4 w1 = *(const float4*)(Wblk + (k+1)*NSV);
                float4 w2 = *(const float4*)(Wblk + (k+2)*NSV);
                float4 w3 = *(const float4*)(Wblk + (k+3)*NSV);
                c4x += m4.x*w0.x + m4.y*w1.x + m4.z*w2.x + m4.w*w3.x;
                c4y += m4.x*w0.y + m4.y*w1.y + m4.z*w2.y + m4.w*w3.y;
                c4z += m4.x*w0.z + m4.y*w1.z + m4.z*w2.z + m4.w*w3.z;
                c4w += m4.x*w0.w + m4.y*w1.w + m4.z*w2.w + m4.w*w3.w;
            }
            c4x += __shfl_xor_sync(0xffffffffu, c4x, 1);
            c4y += __shfl_xor_sync(0xffffffffu, c4y, 1);
            c4z += __shfl_xor_sync(0xffffffffu, c4z, 1);
            c4w += __shfl_xor_sync(0xffffffffu, c4w, 1);
            if (ckh == 0) {
                float vx = c4x, vy = c4y;
                if (bh == 0) { vx += bias[ccA];   vy += bias[ccA+1]; }
                float2 cv; cv.x = vx; cv.y = vy;
                *(float2*)(com + bh*256 + ccA) = cv;
            } else {
                float vz = c4z, vw = c4w;
                if (bh == 0) { vz += bias[ccA+2]; vw += bias[ccA+3]; }
                float2 cv; cv.x = vz; cv.y = vw;
                *(float2*)(com + bh*256 + ccA + 2) = cv;
            }
        }

        // ---- main GEMM: 8 electrons x 4 adjacent cols, half k (warp k-split) ----
        float acc0[8], acc1[8], acc2[8], acc3[8];
        #pragma unroll
        for (int e = 0; e < 8; e++) { acc0[e]=0.f; acc1[e]=0.f; acc2[e]=0.f; acc3[e]=0.f; }
        {
            const float* Wc = W + (size_t)kbase*NSV + cA;
            const float* sv = s_v + ebase*NSV + kbase;
            for (int k = 0; k < 128; k += 4) {
                float4 w0 = *(const float4*)(Wc + (k+0)*NSV);
                float4 w1 = *(const float4*)(Wc + (k+1)*NSV);
                float4 w2 = *(const float4*)(Wc + (k+2)*NSV);
                float4 w3 = *(const float4*)(Wc + (k+3)*NSV);
                #pragma unroll
                for (int e = 0; e < 8; e++) {
                    float4 s4 = *(const float4*)(sv + e*NSV + k);
                    acc0[e] += s4.x*w0.x + s4.y*w1.x + s4.z*w2.x + s4.w*w3.x;
                    acc1[e] += s4.x*w0.y + s4.y*w1.y + s4.z*w2.y + s4.w*w3.y;
                    acc2[e] += s4.x*w0.z + s4.y*w1.z + s4.z*w2.z + s4.w*w3.z;
                    acc3[e] += s4.x*w0.w + s4.y*w1.w + s4.z*w2.w + s4.w*w3.w;
                }
            }
        }
        // ---- pair block: kh=0 -> pu, kh=1 -> pd ----
        {
            const float* Wp = W + (size_t)(768 + kh*32) * NSV + cA;
            const float* pv = (kh ? pd : pu) + ebase*NPV;
            for (int k = 0; k < 32; k += 4) {
                float4 w0 = *(const float4*)(Wp + (k+0)*NSV);
                float4 w1 = *(const float4*)(Wp + (k+1)*NSV);
                float4 w2 = *(const float4*)(Wp + (k+2)*NSV);
                float4 w3 = *(const float4*)(Wp + (k+3)*NSV);
                #pragma unroll
                for (int e = 0; e < 8; e++) {
                    float4 a4 = *(const float4*)(pv + e*NPV + k);
                    acc0[e] += a4.x*w0.x + a4.y*w1.x + a4.z*w2.x + a4.w*w3.x;
                    acc1[e] += a4.x*w0.y + a4.y*w1.y + a4.z*w2.y + a4.w*w3.y;
                    acc2[e] += a4.x*w0.z + a4.y*w1.z + a4.z*w2.z + a4.w*w3.z;
                    acc3[e] += a4.x*w0.w + a4.y*w1.w + a4.z*w2.w + a4.w*w3.w;
                }
            }
        }
        // ---- kh=1 warps export partials to scratch ----
        if (kh) {
            #pragma unroll
            for (int e = 0; e < 8; e++) {
                float4 v; v.x = acc0[e]; v.y = acc1[e]; v.z = acc2[e]; v.w = acc3[e];
                *(float4*)(scr + (e*128 + pid)*4) = v;
            }
        }

        __syncthreads();   // s_v/pu/pd reads, com writes, partial stores complete

        // ---- kh=0 warps: combine partials, writeback + pu/pd deferred stores ----
        if (kh == 0) {
            float4 cm0 = *(const float4*)(com + cA);
            float4 cm1 = *(const float4*)(com + 256 + cA);
            const float cmx = cm0.x + cm1.x;
            const float cmy = cm0.y + cm1.y;
            const float cmz = cm0.z + cm1.z;
            const float cmw = cm0.w + cm1.w;
            if (!isV) {
                #pragma unroll
                for (int e = 0; e < 8; e++) {
                    float4 p = *(const float4*)(scr + (e*128 + pid)*4);
                    float* dst = s_v + (ebase+e)*NSV + cA;
                    float4 old = *(const float4*)dst;
                    float4 nv;
                    nv.x = tanh_fast(acc0[e] + p.x + cmx) + old.x;
                    nv.y = tanh_fast(acc1[e] + p.y + cmy) + old.y;
                    nv.z = tanh_fast(acc2[e] + p.z + cmz) + old.z;
                    nv.w = tanh_fast(acc3[e] + p.w + cmw) + old.w;
                    *(float4*)dst = nv;
                }
            } else {
                #pragma unroll
                for (int e = 0; e < 8; e++) {
                    float4 p = *(const float4*)(scr + (e*128 + pid)*4);
                    float4 nv;
                    nv.x = tanh_fast(acc0[e] + p.x + cmx);
                    nv.y = tanh_fast(acc1[e] + p.y + cmy);
                    nv.z = tanh_fast(acc2[e] + p.z + cmz);
                    nv.w = tanh_fast(acc3[e] + p.w + cmw);
                    *(float4*)(s_v + (ebase+e)*NSV + cA) = nv;
                }
                if (t < 16) {   // env recompute (mu dead after v-layer common)
                    const float* rg = r + b*48 + t*3;
                    float ex = rg[0], ey = rg[1], ez = rg[2];
                    float s = 0.f;
                    #pragma unroll
                    for (int atom = 0; atom < NA; atom++) {
                        float dx = ex - a[atom*3+0];
                        float dy = ey - a[atom*3+1];
                        float dz = ez - a[atom*3+2];
                        s += __expf(-sqrtf(dx*dx + dy*dy + dz*dz));
                    }
                    env[t] = s;
                }
            }
        }
        if (!isV) {
            // deferred pu/pd stores (all threads; partials from p-stream phase)
            const int c2 = t & 31, wp = t >> 5;
            pu[wp*NPV + c2]     = puA * 0.125f;
            pu[(wp+8)*NPV + c2] = puB * 0.125f;
            pd[wp*NPV + c2]     = pdA * 0.125f;
            pd[(wp+8)*NPV + c2] = pdB * 0.125f;
        }
        __syncthreads();

        if (!isV) {
            // ---- mu/md stats pass: thread t = column t ----
            const int c = t;
            float su = 0.f, sd2 = 0.f;
            #pragma unroll
            for (int e = 0; e < NU; e++)  su  += s_v[e*NSV + c];
            #pragma unroll
            for (int e = NU; e < NE; e++) sd2 += s_v[e*NSV + c];
            mu[c] = su * 0.125f;
            md[c] = sd2 * 0.125f;
            __syncthreads();
        }
    }
    // p_v dead; detS aliases its storage.

    // ---------------- orbitals: (spin, k half, col pair) with warp k-split ----------------
    {
        const int osp  = t >> 7;           // spin (warp-uniform)
        const int okh  = (t >> 6) & 1;     // k half (warp-uniform)
        const int ocp  = t & 63;           // col pair within spin's 128
        const int ocA  = ocp * 2;
        const int okb  = okh * 128;
        const int opid = osp * 64 + ocp;   // 0..127
        const float* W    = osp ? wdW : wuW;
        const float* bias = osp ? wdb : wub;
        const int eb2 = osp * 8;

        float oa0[8], oa1[8];
        #pragma unroll
        for (int ii = 0; ii < 8; ii++) { oa0[ii] = 0.f; oa1[ii] = 0.f; }
        const float* Wc2 = W + (size_t)okb * 128 + ocA;
        const float* sv2 = s_v + eb2*NSV + okb;
        for (int k = 0; k < 128; k += 4) {
            float2 w0 = *(const float2*)(Wc2 + (k+0)*128);
            float2 w1 = *(const float2*)(Wc2 + (k+1)*128);
            float2 w2 = *(const float2*)(Wc2 + (k+2)*128);
            float2 w3 = *(const float2*)(Wc2 + (k+3)*128);
            #pragma unroll
            for (int ii = 0; ii < 8; ii++) {
                float4 s4 = *(const float4*)(sv2 + ii*NSV + k);
                oa0[ii] += s4.x*w0.x + s4.y*w1.x + s4.z*w2.x + s4.w*w3.x;
                oa1[ii] += s4.x*w0.y + s4.y*w1.y + s4.z*w2.y + s4.w*w3.y;
            }
        }
        if (okh) {
            #pragma unroll
            for (int ii = 0; ii < 8; ii++) {
                float2 v; v.x = oa0[ii]; v.y = oa1[ii];
                *(float2*)(scr + (ii*128 + opid)*2) = v;
            }
        }
        __syncthreads();
        if (okh == 0) {
            const int col0 = ocA, col1 = ocA + 1;
            const int d0 = col0 & 15, j0 = col0 >> 4;
            const int d1 = col1 & 15, j1 = col1 >> 4;
            const int det0 = osp * NDET + d0;
            const int det1 = osp * NDET + d1;
            const float bs0 = bias[col0], bs1 = bias[col1];
            #pragma unroll
            for (int ii = 0; ii < 8; ii++) {
                float2 p = *(const float2*)(scr + (ii*128 + opid)*2);
                const float ev = env[osp*8 + ii];
                detS[det0*65 + ii*8 + j0] = (oa0[ii] + p.x + bs0) * ev;
                detS[det1*65 + ii*8 + j1] = (oa1[ii] + p.y + bs1) * ev;
            }
        }
    }
    __syncthreads();

    // ---------------- slogdet: 8x8 LU with partial pivoting ----------------
    if (t < 32) {
        float* M = detS + t * 65;
        float sg = 1.f, ld = 0.f;
        for (int k = 0; k < 8; k++) {
            int p = k; float best = fabsf(M[k*8 + k]);
            for (int rr2 = k + 1; rr2 < 8; rr2++) {
                float v = fabsf(M[rr2*8 + k]);
                if (v > best) { best = v; p = rr2; }
            }
            if (p != k) {
                for (int cc = 0; cc < 8; cc++) {
                    float tmp = M[k*8 + cc]; M[k*8 + cc] = M[p*8 + cc]; M[p*8 + cc] = tmp;
                }
                sg = -sg;
            }
            float piv = M[k*8 + k];
            if (piv < 0.f) sg = -sg;
            ld += logf(fabsf(piv));
            float inv = 1.f / piv;
            for (int rr2 = k + 1; rr2 < 8; rr2++) {
                float f = M[rr2*8 + k] * inv;
                for (int cc = k + 1; cc < 8; cc++) M[rr2*8 + cc] -= f * M[k*8 + cc];
            }
        }
        logd_s[t] = ld; sign_s[t] = sg;
    }
    __syncthreads();

    // ---------------- combine ----------------
    if (t == 0) {
        float lds[NDET], sgs[NDET], m = -1e30f;
        #pragma unroll
        for (int d = 0; d < NDET; d++) {
            lds[d] = logd_s[d] + logd_s[NDET + d];
            sgs[d] = sign_s[d] * sign_s[NDET + d];
            if (lds[d] > m) m = lds[d];
        }
        float sum = 0.f;
        #pragma unroll
        for (int d = 0; d < NDET; d++)
            sum += sgs[d] * expf(lds[d] - m) * wfW[d];
        out[b] = logf(fabsf(sum)) + m;
    }
}

extern "C" void kernel_launch(void* const* d_in, const int* in_sizes, int n_in,
                              void* d_out, int out_size)
{
    const float* r   = (const float*)d_in[0];
    const float* a   = (const float*)d_in[1];
    const float* sW0 = (const float*)d_in[2];
    const float* sb0 = (const float*)d_in[3];
    const float* sW  = (const float*)d_in[4];
    const float* sb  = (const float*)d_in[5];
    const float* pW0 = (const float*)d_in[6];
    const float* pb0 = (const float*)d_in[7];
    const float* pW  = (const float*)d_in[8];
    const float* pb  = (const float*)d_in[9];
    const float* vW  = (const float*)d_in[10];
    const float* vb  = (const float*)d_in[11];
    const float* wuW = (const float*)d_in[12];
    const float* wub = (const float*)d_in[13];
    const float* wdW = (const float*)d_in[14];
    const float* wdb = (const float*)d_in[15];
    const float* wfW = (const float*)d_in[16];
    float* out = (float*)d_out;

    const int B = in_sizes[0] / (NE * 3);

    cudaFuncSetAttribute(ansatz_kernel,
                         cudaFuncAttributeMaxDynamicSharedMemorySize, SMEM_BYTES);
    ansatz_kernel<<<B, 256, SMEM_BYTES>>>(r, a, sW0, sb0, sW, sb, pW0, pb0,
                                          pW, pb, vW, vb, wuW, wub, wdW, wdb,
                                          wfW, out);
}